// round 12
// baseline (speedup 1.0000x reference)
#include <cuda_runtime.h>

#define B_    256
#define N_    8192
#define DK_   128
#define DIN_  512
#define OUTD_ 134
#define NS_   5
#define TILE_ 2048   // elements per k4 block
#define BB_   8      // batches per worker group
#define KP_   1024   // per-warp partials per batch (128 blocks x 8 warps)

// ---- device scratch ----
__device__ float g_escores[B_ * N_];
__device__ float g_q[B_ * DK_];           // query pre-scaled by 1/sqrt(dk)
__device__ float g_shift[B_ * NS_];
__device__ float g_gate[B_];
__device__ float g_partial[B_ * KP_];
__device__ int   g_cnt[B_ / BB_];         // per-group worker arrivals (reset by k4)

__device__ __forceinline__ float warp_sum(float v) {
#pragma unroll
    for (int o = 16; o; o >>= 1) v += __shfl_xor_sync(0xffffffffu, v, o);
    return v;
}

// ---- head GEMM fragment: one block handles outputs [8wx,8wx+8) x batches [b0,b0+8) ----
__device__ void head_work(int wx, int b0,
                          const float* __restrict__ inp,
                          const float* __restrict__ W,
                          const float* __restrict__ bias) {
    __shared__ float s_in[BB_][DIN_];
    __shared__ float s_tail[BB_][6];
    const int tid = threadIdx.x;
    const int warp = tid >> 5, lane = tid & 31;

    {
        const float4* ip = reinterpret_cast<const float4*>(inp + (size_t)b0 * DIN_);
        float4* sp = &reinterpret_cast<float4(*)[DIN_ / 4]>(s_in)[0][0];
#pragma unroll
        for (int i = 0; i < 4; i++) sp[tid + i * 256] = ip[tid + i * 256];
    }
    __syncthreads();

    const int o = wx * 8 + warp;
    if (o < OUTD_) {
        const float4* wr = reinterpret_cast<const float4*>(W + (size_t)o * DIN_);
        float4 w[4];
#pragma unroll
        for (int j = 0; j < 4; j++) w[j] = wr[lane + 32 * j];

        float acc[BB_];
#pragma unroll
        for (int bb = 0; bb < BB_; bb++) acc[bb] = 0.f;
#pragma unroll
        for (int j = 0; j < 4; j++) {
#pragma unroll
            for (int bb = 0; bb < BB_; bb++) {
                const float4 x = reinterpret_cast<const float4*>(s_in[bb])[lane + 32 * j];
                acc[bb] = fmaf(w[j].x, x.x,
                           fmaf(w[j].y, x.y,
                            fmaf(w[j].z, x.z,
                             fmaf(w[j].w, x.w, acc[bb]))));
            }
        }
        const float bo = bias[o];
#pragma unroll
        for (int bb = 0; bb < BB_; bb++) {
            float s = warp_sum(acc[bb]);
            if (lane == 0) {
                s += bo;
                if (o < DK_)
                    g_q[(size_t)(b0 + bb) * DK_ + o] = s * 0.088388347648318447f;
                else
                    s_tail[bb][o - DK_] = s;
            }
        }
    }
    if (wx == 16) {
        __syncthreads();
        if (tid < BB_) {
            const int b = b0 + tid;
            g_gate[b] = 1.f / (1.f + __expf(-s_tail[tid][0]));
            float mx = s_tail[tid][1];
#pragma unroll
            for (int s = 2; s <= NS_; s++) mx = fmaxf(mx, s_tail[tid][s]);
            float e[NS_], sum = 0.f;
#pragma unroll
            for (int s = 0; s < NS_; s++) { e[s] = __expf(s_tail[tid][1 + s] - mx); sum += e[s]; }
            float inv = 1.f / sum;
#pragma unroll
            for (int s = 0; s < NS_; s++) g_shift[b * NS_ + s] = e[s] * inv;
        }
    }
}

// ---- K2: fused head + streaming scores. Grid (128, 256), 256 threads ----
// Workers (x<17, y%8==0) compute the head GEMM for their batch group, arrive
// on g_cnt[group]; every block gates on g_cnt[group]==17 before reading g_q.
__global__ void k2_scores(const float* __restrict__ mem,
                          const float* __restrict__ inp,
                          const float* __restrict__ W,
                          const float* __restrict__ bias) {
    const int b = blockIdx.y, tid = threadIdx.x;
    const int warp = tid >> 5, lane = tid & 31;
    const int grp = b >> 3;
    const bool is_worker = (blockIdx.x < 17) && ((b & 7) == 0);

    const int n0 = blockIdx.x * 64 + warp * 8;
    const float4* mp = reinterpret_cast<const float4*>(mem)
                       + ((size_t)b * N_ + n0) * (DK_ / 4) + lane;
    float4 m[8];

    if (is_worker) {
        head_work(blockIdx.x, grp * BB_, inp, W, bias);
        __threadfence();
        if (tid == 0) atomicAdd(&g_cnt[grp], 1);
        // spin for the whole group (incl. the other 16 workers)
        if (tid == 0) { while (atomicAdd(&g_cnt[grp], 0) < 17) { } }
        __syncthreads();
        __threadfence();
#pragma unroll
        for (int r = 0; r < 8; r++) m[r] = __ldcs(mp + 32 * r);
    } else {
        // prefetch the streaming rows (independent of the gate), then spin
#pragma unroll
        for (int r = 0; r < 8; r++) m[r] = __ldcs(mp + 32 * r);
        if (tid == 0) { while (atomicAdd(&g_cnt[grp], 0) < 17) { } }
        __syncthreads();
        __threadfence();
    }

    const float4 q4 = *reinterpret_cast<const float4*>(g_q + (size_t)b * DK_ + lane * 4);
    float d[8];
#pragma unroll
    for (int r = 0; r < 8; r++)
        d[r] = m[r].x * q4.x + m[r].y * q4.y + m[r].z * q4.z + m[r].w * q4.w;
#pragma unroll
    for (int r = 0; r < 8; r++) d[r] = warp_sum(d[r]);
    if (lane == 0) {
        float e[8];
#pragma unroll
        for (int r = 0; r < 8; r++) e[r] = __expf(d[r]);
        float* sc = g_escores + (size_t)b * N_ + n0;
        *reinterpret_cast<float4*>(sc)     = make_float4(e[0], e[1], e[2], e[3]);
        *reinterpret_cast<float4*>(sc + 4) = make_float4(e[4], e[5], e[6], e[7]);
        float t = 0.f;
#pragma unroll
        for (int r = 0; r < 8; r++) t += e[r];
        g_partial[b * KP_ + blockIdx.x * 8 + warp] = t;  // fixed slot -> deterministic
    }
}

// ---- K4: fused Z-reduce + interp + 5-tap circular shift; also resets g_cnt ----
__global__ void k4_out(const float* __restrict__ prev, float* __restrict__ out) {
    __shared__ float s_int[TILE_ + 8];
    __shared__ float s_sh[NS_];
    __shared__ float s_red[8];
    __shared__ float s_c[2];
    const int b = blockIdx.y, tid = threadIdx.x;
    const int warp = tid >> 5, lane = tid & 31;
    const int base = blockIdx.x * TILE_;

    // independent of k2: prev body + halo (read-once -> evict-first)
    const float4* pp = reinterpret_cast<const float4*>(prev + (size_t)b * N_ + base);
    float4 pr[TILE_ / 1024];
#pragma unroll
    for (int i = 0; i < TILE_ / 1024; i++) pr[i] = __ldcs(pp + tid + i * 256);
    float pr_halo = 0.f;
    int hk = 0;
    if (tid < 4) {
        hk = (tid < 2) ? (tid - 2) : (TILE_ + tid - 2);
        pr_halo = prev[(size_t)b * N_ + ((base + hk + N_) & (N_ - 1))];
    }

    cudaGridDependencySynchronize();   // wait for k2

    // reset worker counters for the next graph replay (k2 fully done by now)
    if (tid == 0 && blockIdx.x == 0 && (b & 7) == 0) g_cnt[b >> 3] = 0;

    // deterministic Z reduce over 1024 per-warp partials
    float p = 0.f;
    const float* gp = g_partial + (size_t)b * KP_;
#pragma unroll
    for (int i = 0; i < 4; i++) p += gp[tid + i * 256];
    p = warp_sum(p);
    if (lane == 0) s_red[warp] = p;
    if (tid < NS_) s_sh[tid] = g_shift[b * NS_ + tid];
    __syncthreads();
    if (tid == 0) {
        float Z = 0.f;
#pragma unroll
        for (int w = 0; w < 8; w++) Z += s_red[w];
        const float g = g_gate[b];
        s_c[0] = g / Z;
        s_c[1] = 1.f - g;
    }
    __syncthreads();
    const float cA = s_c[0], cB = s_c[1];

    const float4* ep = reinterpret_cast<const float4*>(g_escores + (size_t)b * N_ + base);
#pragma unroll
    for (int i = 0; i < TILE_ / 1024; i++) {
        const int v = tid + i * 256;
        const float4 e = __ldcs(ep + v);
        float4 r;
        r.x = cA * e.x + cB * pr[i].x;
        r.y = cA * e.y + cB * pr[i].y;
        r.z = cA * e.z + cB * pr[i].z;
        r.w = cA * e.w + cB * pr[i].w;
        *reinterpret_cast<float4*>(s_int + 4 + v * 4) = r;
    }
    if (tid < 4) {
        const int n = (base + hk + N_) & (N_ - 1);
        s_int[4 + hk] = cA * g_escores[(size_t)b * N_ + n] + cB * pr_halo;
    }
    __syncthreads();

    const float sh0 = s_sh[0], sh1 = s_sh[1], sh2 = s_sh[2], sh3 = s_sh[3], sh4 = s_sh[4];
    float4* op = reinterpret_cast<float4*>(out + (size_t)b * N_ + base);
    const float4* si4 = reinterpret_cast<const float4*>(s_int);
#pragma unroll
    for (int i = 0; i < TILE_ / 1024; i++) {
        const int v = tid + i * 256;
        const float4 f0 = si4[v];
        const float4 f1 = si4[v + 1];
        const float4 f2 = si4[v + 2];
        float4 o;
        o.x = sh0 * f0.z + sh1 * f0.w + sh2 * f1.x + sh3 * f1.y + sh4 * f1.z;
        o.y = sh0 * f0.w + sh1 * f1.x + sh2 * f1.y + sh3 * f1.z + sh4 * f1.w;
        o.z = sh0 * f1.x + sh1 * f1.y + sh2 * f1.z + sh3 * f1.w + sh4 * f2.x;
        o.w = sh0 * f1.y + sh1 * f1.z + sh2 * f1.w + sh3 * f2.x + sh4 * f2.y;
        __stcs(op + v, o);
    }
}

extern "C" void kernel_launch(void* const* d_in, const int* in_sizes, int n_in,
                              void* d_out, int out_size) {
    const float* inp  = (const float*)d_in[0];
    const float* mem  = (const float*)d_in[1];
    const float* prev = (const float*)d_in[2];
    const float* W    = (const float*)d_in[3];
    const float* bias = (const float*)d_in[4];
    float* out = (float*)d_out;

    k2_scores<<<dim3(N_ / 64, B_), 256>>>(mem, inp, W, bias);

    cudaLaunchAttribute attrs[1];
    attrs[0].id = cudaLaunchAttributeProgrammaticStreamSerialization;
    attrs[0].val.programmaticStreamSerializationAllowed = 1;

    cudaLaunchConfig_t cfg = {};
    cfg.gridDim = dim3(N_ / TILE_, B_);
    cfg.blockDim = dim3(256, 1, 1);
    cfg.attrs = attrs;
    cfg.numAttrs = 1;
    cudaLaunchKernelEx(&cfg, k4_out, prev, out);
}

// round 13
// speedup vs baseline: 1.7220x; 1.7220x over previous
#include <cuda_runtime.h>

#define B_    256
#define N_    8192
#define DK_   128
#define DIN_  512
#define OUTD_ 134
#define NS_   5
#define TILE_ 2048   // elements per k4 block
#define BB_   8      // batches per k1 block
#define KP_   128    // per-block partials per batch

// ---- device scratch ----
__device__ float g_escores[B_ * N_];
__device__ float g_q[B_ * DK_];           // query pre-scaled by 1/sqrt(dk)
__device__ float g_shift[B_ * NS_];
__device__ float g_gate[B_];
__device__ float g_partial[B_ * KP_];
__device__ float g_coefA[B_];
__device__ float g_coefB[B_];
__device__ int   g_zcnt[B_];              // k2 block arrivals per batch (reset by k4)

__device__ __forceinline__ float warp_sum(float v) {
#pragma unroll
    for (int o = 16; o; o >>= 1) v += __shfl_xor_sync(0xffffffffu, v, o);
    return v;
}

// ---- K1: head GEMM with 8-batch W reuse; grid (17, 32), 256 threads ----
__global__ void k1_head(const float* __restrict__ inp,
                        const float* __restrict__ W,
                        const float* __restrict__ bias) {
    __shared__ float s_in[BB_][DIN_];
    __shared__ float s_tail[BB_][6];
    const int tid = threadIdx.x;
    const int warp = tid >> 5, lane = tid & 31;
    const int b0 = blockIdx.y * BB_;

    {
        const float4* ip = reinterpret_cast<const float4*>(inp + (size_t)b0 * DIN_);
        float4* sp = &reinterpret_cast<float4(*)[DIN_ / 4]>(s_in)[0][0];
#pragma unroll
        for (int i = 0; i < 4; i++) sp[tid + i * 256] = ip[tid + i * 256];
    }
    __syncthreads();

    const int o = blockIdx.x * 8 + warp;
    if (o < OUTD_) {
        const float4* wr = reinterpret_cast<const float4*>(W + (size_t)o * DIN_);
        float4 w[4];
#pragma unroll
        for (int j = 0; j < 4; j++) w[j] = wr[lane + 32 * j];

        float acc[BB_];
#pragma unroll
        for (int bb = 0; bb < BB_; bb++) acc[bb] = 0.f;
#pragma unroll
        for (int j = 0; j < 4; j++) {
#pragma unroll
            for (int bb = 0; bb < BB_; bb++) {
                const float4 x = reinterpret_cast<const float4*>(s_in[bb])[lane + 32 * j];
                acc[bb] = fmaf(w[j].x, x.x,
                           fmaf(w[j].y, x.y,
                            fmaf(w[j].z, x.z,
                             fmaf(w[j].w, x.w, acc[bb]))));
            }
        }
        const float bo = bias[o];
#pragma unroll
        for (int bb = 0; bb < BB_; bb++) {
            float s = warp_sum(acc[bb]);
            if (lane == 0) {
                s += bo;
                if (o < DK_)
                    g_q[(size_t)(b0 + bb) * DK_ + o] = s * 0.088388347648318447f;
                else
                    s_tail[bb][o - DK_] = s;
            }
        }
    }
    if (blockIdx.x == 16) {
        __syncthreads();
        if (tid < BB_) {
            const int b = b0 + tid;
            g_gate[b] = 1.f / (1.f + __expf(-s_tail[tid][0]));
            float mx = s_tail[tid][1];
#pragma unroll
            for (int s = 2; s <= NS_; s++) mx = fmaxf(mx, s_tail[tid][s]);
            float e[NS_], sum = 0.f;
#pragma unroll
            for (int s = 0; s < NS_; s++) { e[s] = __expf(s_tail[tid][1 + s] - mx); sum += e[s]; }
            float inv = 1.f / sum;
#pragma unroll
            for (int s = 0; s < NS_; s++) g_shift[b * NS_ + s] = e[s] * inv;
        }
    }
}

// ---- K2: streaming scores + last-block Z finalize; PDL overlap with k1 ----
__global__ void k2_scores(const float* __restrict__ mem) {
    __shared__ float s_ws[8];
    __shared__ int   s_last;
    const int b = blockIdx.y, tid = threadIdx.x;
    const int warp = tid >> 5, lane = tid & 31;
    const int n0 = blockIdx.x * 64 + warp * 8;
    const float4* mp = reinterpret_cast<const float4*>(mem)
                       + ((size_t)b * N_ + n0) * (DK_ / 4) + lane;
    float4 m[8];
#pragma unroll
    for (int r = 0; r < 8; r++) m[r] = __ldcs(mp + 32 * r);   // evict-first

    cudaGridDependencySynchronize();   // wait for k1's g_q

    const float4 q4 = *reinterpret_cast<const float4*>(g_q + (size_t)b * DK_ + lane * 4);
    float d[8];
#pragma unroll
    for (int r = 0; r < 8; r++)
        d[r] = m[r].x * q4.x + m[r].y * q4.y + m[r].z * q4.z + m[r].w * q4.w;
#pragma unroll
    for (int r = 0; r < 8; r++) d[r] = warp_sum(d[r]);
    if (lane == 0) {
        float e[8];
#pragma unroll
        for (int r = 0; r < 8; r++) e[r] = __expf(d[r]);
        float* sc = g_escores + (size_t)b * N_ + n0;
        *reinterpret_cast<float4*>(sc)     = make_float4(e[0], e[1], e[2], e[3]);
        *reinterpret_cast<float4*>(sc + 4) = make_float4(e[4], e[5], e[6], e[7]);
        float t = 0.f;
#pragma unroll
        for (int r = 0; r < 8; r++) t += e[r];
        s_ws[warp] = t;
    }
    __syncthreads();
    if (tid == 0) {
        float t = 0.f;
#pragma unroll
        for (int w = 0; w < 8; w++) t += s_ws[w];
        g_partial[b * KP_ + blockIdx.x] = t;   // fixed slot -> deterministic
        __threadfence();
        s_last = (atomicAdd(&g_zcnt[b], 1) == KP_ - 1);
    }
    __syncthreads();
    if (s_last) {
        // exactly one block per batch; all 128 partials globally visible.
        __shared__ float s_red[4];
        float p = (tid < KP_) ? __ldcg(g_partial + b * KP_ + tid) : 0.f;
        p = warp_sum(p);
        if (lane == 0 && warp < 4) s_red[warp] = p;
        __syncthreads();
        if (tid == 0) {
            const float Z = (s_red[0] + s_red[1]) + (s_red[2] + s_red[3]);
            const float g = g_gate[b];
            g_coefA[b] = g / Z;
            g_coefB[b] = 1.f - g;
        }
    }
}

// ---- K4: interp + 5-tap circular shift, 2048 elems/block; PDL ----
__global__ void k4_out(const float* __restrict__ prev, float* __restrict__ out) {
    __shared__ float s_int[TILE_ + 8];
    __shared__ float s_sh[NS_];
    const int b = blockIdx.y, tid = threadIdx.x;
    const int base = blockIdx.x * TILE_;

    // independent of k2: prev body + halo (read-once -> evict-first)
    const float4* pp = reinterpret_cast<const float4*>(prev + (size_t)b * N_ + base);
    float4 pr[TILE_ / 1024];
#pragma unroll
    for (int i = 0; i < TILE_ / 1024; i++) pr[i] = __ldcs(pp + tid + i * 256);
    float pr_halo = 0.f;
    int hk = 0;
    if (tid < 4) {
        hk = (tid < 2) ? (tid - 2) : (TILE_ + tid - 2);
        pr_halo = prev[(size_t)b * N_ + ((base + hk + N_) & (N_ - 1))];
    }

    cudaGridDependencySynchronize();   // wait for k2 (escores + coefs)

    if (tid == 0 && blockIdx.x == 0) g_zcnt[b] = 0;   // reset for next replay
    if (tid < NS_) s_sh[tid] = g_shift[b * NS_ + tid];
    const float cA = g_coefA[b], cB = g_coefB[b];

    const float4* ep = reinterpret_cast<const float4*>(g_escores + (size_t)b * N_ + base);
#pragma unroll
    for (int i = 0; i < TILE_ / 1024; i++) {
        const int v = tid + i * 256;
        const float4 e = __ldcs(ep + v);
        float4 r;
        r.x = cA * e.x + cB * pr[i].x;
        r.y = cA * e.y + cB * pr[i].y;
        r.z = cA * e.z + cB * pr[i].z;
        r.w = cA * e.w + cB * pr[i].w;
        *reinterpret_cast<float4*>(s_int + 4 + v * 4) = r;
    }
    if (tid < 4) {
        const int n = (base + hk + N_) & (N_ - 1);
        s_int[4 + hk] = cA * g_escores[(size_t)b * N_ + n] + cB * pr_halo;
    }
    __syncthreads();

    const float sh0 = s_sh[0], sh1 = s_sh[1], sh2 = s_sh[2], sh3 = s_sh[3], sh4 = s_sh[4];
    float4* op = reinterpret_cast<float4*>(out + (size_t)b * N_ + base);
    const float4* si4 = reinterpret_cast<const float4*>(s_int);
#pragma unroll
    for (int i = 0; i < TILE_ / 1024; i++) {
        const int v = tid + i * 256;
        const float4 f0 = si4[v];
        const float4 f1 = si4[v + 1];
        const float4 f2 = si4[v + 2];
        float4 o;
        o.x = sh0 * f0.z + sh1 * f0.w + sh2 * f1.x + sh3 * f1.y + sh4 * f1.z;
        o.y = sh0 * f0.w + sh1 * f1.x + sh2 * f1.y + sh3 * f1.z + sh4 * f1.w;
        o.z = sh0 * f1.x + sh1 * f1.y + sh2 * f1.z + sh3 * f1.w + sh4 * f2.x;
        o.w = sh0 * f1.y + sh1 * f1.z + sh2 * f1.w + sh3 * f2.x + sh4 * f2.y;
        __stcs(op + v, o);
    }
}

extern "C" void kernel_launch(void* const* d_in, const int* in_sizes, int n_in,
                              void* d_out, int out_size) {
    const float* inp  = (const float*)d_in[0];
    const float* mem  = (const float*)d_in[1];
    const float* prev = (const float*)d_in[2];
    const float* W    = (const float*)d_in[3];
    const float* bias = (const float*)d_in[4];
    float* out = (float*)d_out;

    k1_head<<<dim3(17, B_ / BB_), 256>>>(inp, W, bias);

    cudaLaunchAttribute attrs[1];
    attrs[0].id = cudaLaunchAttributeProgrammaticStreamSerialization;
    attrs[0].val.programmaticStreamSerializationAllowed = 1;

    {
        cudaLaunchConfig_t cfg = {};
        cfg.gridDim = dim3(N_ / 64, B_);
        cfg.blockDim = dim3(256, 1, 1);
        cfg.attrs = attrs;
        cfg.numAttrs = 1;
        cudaLaunchKernelEx(&cfg, k2_scores, mem);
    }
    {
        cudaLaunchConfig_t cfg = {};
        cfg.gridDim = dim3(N_ / TILE_, B_);
        cfg.blockDim = dim3(256, 1, 1);
        cfg.attrs = attrs;
        cfg.numAttrs = 1;
        cudaLaunchKernelEx(&cfg, k4_out, prev, out);
    }
}

// round 14
// speedup vs baseline: 1.7434x; 1.0124x over previous
#include <cuda_runtime.h>

#define B_    256
#define N_    8192
#define DK_   128
#define DIN_  512
#define OUTD_ 134
#define NS_   5
#define TILE_ 2048   // elements per k4 block
#define BB_   8      // batches per k1 block
#define KP_   1024   // per-warp partials per batch (128 blocks x 8 warps)

// ---- device scratch ----
__device__ float g_escores[B_ * N_];
__device__ float g_q[B_ * DK_];           // query pre-scaled by 1/sqrt(dk)
__device__ float g_shift[B_ * NS_];
__device__ float g_gate[B_];
__device__ float g_partial[B_ * KP_];

__device__ __forceinline__ float warp_sum(float v) {
#pragma unroll
    for (int o = 16; o; o >>= 1) v += __shfl_xor_sync(0xffffffffu, v, o);
    return v;
}

// ---- K1: head GEMM with 8-batch W reuse; grid (17, 32), 256 threads ----
// W register loads issue BEFORE the input-smem barrier: the two cold-DRAM
// fetches (inp, W) overlap instead of serializing.
__global__ void k1_head(const float* __restrict__ inp,
                        const float* __restrict__ W,
                        const float* __restrict__ bias) {
    __shared__ float s_in[BB_][DIN_];
    __shared__ float s_tail[BB_][6];
    const int tid = threadIdx.x;
    const int warp = tid >> 5, lane = tid & 31;
    const int b0 = blockIdx.y * BB_;
    const int o = blockIdx.x * 8 + warp;

    // issue W loads first (independent of smem / barrier)
    float4 w[4];
    if (o < OUTD_) {
        const float4* wr = reinterpret_cast<const float4*>(W + (size_t)o * DIN_);
#pragma unroll
        for (int j = 0; j < 4; j++) w[j] = wr[lane + 32 * j];
    }
    const float bo = (o < OUTD_) ? bias[o] : 0.f;

    {
        const float4* ip = reinterpret_cast<const float4*>(inp + (size_t)b0 * DIN_);
        float4* sp = &reinterpret_cast<float4(*)[DIN_ / 4]>(s_in)[0][0];
#pragma unroll
        for (int i = 0; i < 4; i++) sp[tid + i * 256] = ip[tid + i * 256];
    }
    __syncthreads();

    if (o < OUTD_) {
        float acc[BB_];
#pragma unroll
        for (int bb = 0; bb < BB_; bb++) acc[bb] = 0.f;
#pragma unroll
        for (int j = 0; j < 4; j++) {
#pragma unroll
            for (int bb = 0; bb < BB_; bb++) {
                const float4 x = reinterpret_cast<const float4*>(s_in[bb])[lane + 32 * j];
                acc[bb] = fmaf(w[j].x, x.x,
                           fmaf(w[j].y, x.y,
                            fmaf(w[j].z, x.z,
                             fmaf(w[j].w, x.w, acc[bb]))));
            }
        }
#pragma unroll
        for (int bb = 0; bb < BB_; bb++) {
            float s = warp_sum(acc[bb]);
            if (lane == 0) {
                s += bo;
                if (o < DK_)
                    g_q[(size_t)(b0 + bb) * DK_ + o] = s * 0.088388347648318447f;
                else
                    s_tail[bb][o - DK_] = s;
            }
        }
    }
    if (blockIdx.x == 16) {
        __syncthreads();
        if (tid < BB_) {
            const int b = b0 + tid;
            g_gate[b] = 1.f / (1.f + __expf(-s_tail[tid][0]));
            float mx = s_tail[tid][1];
#pragma unroll
            for (int s = 2; s <= NS_; s++) mx = fmaxf(mx, s_tail[tid][s]);
            float e[NS_], sum = 0.f;
#pragma unroll
            for (int s = 0; s < NS_; s++) { e[s] = __expf(s_tail[tid][1 + s] - mx); sum += e[s]; }
            float inv = 1.f / sum;
#pragma unroll
            for (int s = 0; s < NS_; s++) g_shift[b * NS_ + s] = e[s] * inv;
        }
    }
}

// ---- K2: streaming (evict-first) reads of memory; PDL overlap with k1 tail ----
__global__ void k2_scores(const float* __restrict__ mem) {
    const int b = blockIdx.y, tid = threadIdx.x;
    const int warp = tid >> 5, lane = tid & 31;
    const int n0 = blockIdx.x * 64 + warp * 8;
    const float4* mp = reinterpret_cast<const float4*>(mem)
                       + ((size_t)b * N_ + n0) * (DK_ / 4) + lane;
    float4 m[8];
#pragma unroll
    for (int r = 0; r < 8; r++) m[r] = __ldcs(mp + 32 * r);   // evict-first

    cudaGridDependencySynchronize();   // wait for k1's g_q

    const float4 q4 = *reinterpret_cast<const float4*>(g_q + (size_t)b * DK_ + lane * 4);
    float d[8];
#pragma unroll
    for (int r = 0; r < 8; r++)
        d[r] = m[r].x * q4.x + m[r].y * q4.y + m[r].z * q4.z + m[r].w * q4.w;
#pragma unroll
    for (int r = 0; r < 8; r++) d[r] = warp_sum(d[r]);
    if (lane == 0) {
        float e[8];
#pragma unroll
        for (int r = 0; r < 8; r++) e[r] = __expf(d[r]);
        float* sc = g_escores + (size_t)b * N_ + n0;
        *reinterpret_cast<float4*>(sc)     = make_float4(e[0], e[1], e[2], e[3]);
        *reinterpret_cast<float4*>(sc + 4) = make_float4(e[4], e[5], e[6], e[7]);
        float t = 0.f;
#pragma unroll
        for (int r = 0; r < 8; r++) t += e[r];
        g_partial[b * KP_ + blockIdx.x * 8 + warp] = t;  // fixed slot -> deterministic
    }
}

// ---- K4: fused Z-reduce + interp + 5-tap circular shift, 2048 elems/block ----
// escores LDGs issue first after the dependency sync; Z-reduce runs under them.
__global__ void k4_out(const float* __restrict__ prev, float* __restrict__ out) {
    __shared__ float s_int[TILE_ + 8];
    __shared__ float s_sh[NS_];
    __shared__ float s_red[8];
    __shared__ float s_c[2];
    const int b = blockIdx.y, tid = threadIdx.x;
    const int warp = tid >> 5, lane = tid & 31;
    const int base = blockIdx.x * TILE_;

    // independent of k2: prev body + halo (read-once -> evict-first)
    const float4* pp = reinterpret_cast<const float4*>(prev + (size_t)b * N_ + base);
    float4 pr[TILE_ / 1024];
#pragma unroll
    for (int i = 0; i < TILE_ / 1024; i++) pr[i] = __ldcs(pp + tid + i * 256);
    float pr_halo = 0.f;
    int hk = 0;
    if (tid < 4) {
        hk = (tid < 2) ? (tid - 2) : (TILE_ + tid - 2);
        pr_halo = prev[(size_t)b * N_ + ((base + hk + N_) & (N_ - 1))];
    }

    cudaGridDependencySynchronize();   // wait for k2

    // issue escores loads FIRST (registers), Z-reduce hides under them
    const float4* ep = reinterpret_cast<const float4*>(g_escores + (size_t)b * N_ + base);
    float4 ev[TILE_ / 1024];
#pragma unroll
    for (int i = 0; i < TILE_ / 1024; i++) ev[i] = __ldcs(ep + tid + i * 256);
    float e_halo = 0.f;
    if (tid < 4) e_halo = g_escores[(size_t)b * N_ + ((base + hk + N_) & (N_ - 1))];

    // deterministic Z reduce over 1024 per-warp partials
    float p = 0.f;
    const float* gp = g_partial + (size_t)b * KP_;
#pragma unroll
    for (int i = 0; i < 4; i++) p += gp[tid + i * 256];
    p = warp_sum(p);
    if (lane == 0) s_red[warp] = p;
    if (tid < NS_) s_sh[tid] = g_shift[b * NS_ + tid];
    __syncthreads();
    if (tid == 0) {
        float Z = 0.f;
#pragma unroll
        for (int w = 0; w < 8; w++) Z += s_red[w];
        const float g = g_gate[b];
        s_c[0] = g / Z;
        s_c[1] = 1.f - g;
    }
    __syncthreads();
    const float cA = s_c[0], cB = s_c[1];

#pragma unroll
    for (int i = 0; i < TILE_ / 1024; i++) {
        const int v = tid + i * 256;
        float4 r;
        r.x = cA * ev[i].x + cB * pr[i].x;
        r.y = cA * ev[i].y + cB * pr[i].y;
        r.z = cA * ev[i].z + cB * pr[i].z;
        r.w = cA * ev[i].w + cB * pr[i].w;
        *reinterpret_cast<float4*>(s_int + 4 + v * 4) = r;
    }
    if (tid < 4) s_int[4 + hk] = cA * e_halo + cB * pr_halo;
    __syncthreads();

    const float sh0 = s_sh[0], sh1 = s_sh[1], sh2 = s_sh[2], sh3 = s_sh[3], sh4 = s_sh[4];
    float4* op = reinterpret_cast<float4*>(out + (size_t)b * N_ + base);
    const float4* si4 = reinterpret_cast<const float4*>(s_int);
#pragma unroll
    for (int i = 0; i < TILE_ / 1024; i++) {
        const int v = tid + i * 256;
        const float4 f0 = si4[v];
        const float4 f1 = si4[v + 1];
        const float4 f2 = si4[v + 2];
        float4 o;
        o.x = sh0 * f0.z + sh1 * f0.w + sh2 * f1.x + sh3 * f1.y + sh4 * f1.z;
        o.y = sh0 * f0.w + sh1 * f1.x + sh2 * f1.y + sh3 * f1.z + sh4 * f1.w;
        o.z = sh0 * f1.x + sh1 * f1.y + sh2 * f1.z + sh3 * f1.w + sh4 * f2.x;
        o.w = sh0 * f1.y + sh1 * f1.z + sh2 * f1.w + sh3 * f2.x + sh4 * f2.y;
        __stcs(op + v, o);
    }
}

extern "C" void kernel_launch(void* const* d_in, const int* in_sizes, int n_in,
                              void* d_out, int out_size) {
    const float* inp  = (const float*)d_in[0];
    const float* mem  = (const float*)d_in[1];
    const float* prev = (const float*)d_in[2];
    const float* W    = (const float*)d_in[3];
    const float* bias = (const float*)d_in[4];
    float* out = (float*)d_out;

    k1_head<<<dim3(17, B_ / BB_), 256>>>(inp, W, bias);

    cudaLaunchAttribute attrs[1];
    attrs[0].id = cudaLaunchAttributeProgrammaticStreamSerialization;
    attrs[0].val.programmaticStreamSerializationAllowed = 1;

    {
        cudaLaunchConfig_t cfg = {};
        cfg.gridDim = dim3(N_ / 64, B_);
        cfg.blockDim = dim3(256, 1, 1);
        cfg.attrs = attrs;
        cfg.numAttrs = 1;
        cudaLaunchKernelEx(&cfg, k2_scores, mem);
    }
    {
        cudaLaunchConfig_t cfg = {};
        cfg.gridDim = dim3(N_ / TILE_, B_);
        cfg.blockDim = dim3(256, 1, 1);
        cfg.attrs = attrs;
        cfg.numAttrs = 1;
        cudaLaunchKernelEx(&cfg, k4_out, prev, out);
    }
}

// round 15
// speedup vs baseline: 1.7479x; 1.0026x over previous
#include <cuda_runtime.h>

#define B_    256
#define N_    8192
#define DK_   128
#define DIN_  512
#define OUTD_ 134
#define NS_   5
#define TILE_ 2048   // elements per k4 block
#define BB_   8      // batches per k1 block
#define KP_   1024   // per-warp partials per batch (128 blocks x 8 warps)

// ---- device scratch ----
__device__ float g_escores[B_ * N_];
__device__ float g_q[B_ * DK_];           // query pre-scaled by 1/sqrt(dk)
__device__ float g_shift[B_ * NS_];
__device__ float g_gate[B_];
__device__ float g_partial[B_ * KP_];

__device__ __forceinline__ float warp_sum(float v) {
#pragma unroll
    for (int o = 16; o; o >>= 1) v += __shfl_xor_sync(0xffffffffu, v, o);
    return v;
}

// ---- K1: head GEMM with 8-batch W reuse; grid (17, 32), 256 threads ----
// Fires the PDL trigger at START: k2 launches + prefetches memory rows while
// k1 computes; k2's grid-sync still waits for g_q completion.
__global__ void k1_head(const float* __restrict__ inp,
                        const float* __restrict__ W,
                        const float* __restrict__ bias) {
    cudaTriggerProgrammaticLaunchCompletion();

    __shared__ float s_in[BB_][DIN_];
    __shared__ float s_tail[BB_][6];
    const int tid = threadIdx.x;
    const int warp = tid >> 5, lane = tid & 31;
    const int b0 = blockIdx.y * BB_;
    const int o = blockIdx.x * 8 + warp;

    // issue W loads first (independent of smem / barrier)
    float4 w[4];
    if (o < OUTD_) {
        const float4* wr = reinterpret_cast<const float4*>(W + (size_t)o * DIN_);
#pragma unroll
        for (int j = 0; j < 4; j++) w[j] = wr[lane + 32 * j];
    }
    const float bo = (o < OUTD_) ? bias[o] : 0.f;

    {
        const float4* ip = reinterpret_cast<const float4*>(inp + (size_t)b0 * DIN_);
        float4* sp = &reinterpret_cast<float4(*)[DIN_ / 4]>(s_in)[0][0];
#pragma unroll
        for (int i = 0; i < 4; i++) sp[tid + i * 256] = ip[tid + i * 256];
    }
    __syncthreads();

    if (o < OUTD_) {
        float acc[BB_];
#pragma unroll
        for (int bb = 0; bb < BB_; bb++) acc[bb] = 0.f;
#pragma unroll
        for (int j = 0; j < 4; j++) {
#pragma unroll
            for (int bb = 0; bb < BB_; bb++) {
                const float4 x = reinterpret_cast<const float4*>(s_in[bb])[lane + 32 * j];
                acc[bb] = fmaf(w[j].x, x.x,
                           fmaf(w[j].y, x.y,
                            fmaf(w[j].z, x.z,
                             fmaf(w[j].w, x.w, acc[bb]))));
            }
        }
#pragma unroll
        for (int bb = 0; bb < BB_; bb++) {
            float s = warp_sum(acc[bb]);
            if (lane == 0) {
                s += bo;
                if (o < DK_)
                    g_q[(size_t)(b0 + bb) * DK_ + o] = s * 0.088388347648318447f;
                else
                    s_tail[bb][o - DK_] = s;
            }
        }
    }
    if (blockIdx.x == 16) {
        __syncthreads();
        if (tid < BB_) {
            const int b = b0 + tid;
            g_gate[b] = 1.f / (1.f + __expf(-s_tail[tid][0]));
            float mx = s_tail[tid][1];
#pragma unroll
            for (int s = 2; s <= NS_; s++) mx = fmaxf(mx, s_tail[tid][s]);
            float e[NS_], sum = 0.f;
#pragma unroll
            for (int s = 0; s < NS_; s++) { e[s] = __expf(s_tail[tid][1 + s] - mx); sum += e[s]; }
            float inv = 1.f / sum;
#pragma unroll
            for (int s = 0; s < NS_; s++) g_shift[b * NS_ + s] = e[s] * inv;
        }
    }
}

// ---- K2: streaming scores; prefetch BEFORE grid-sync; early trigger for k4 ----
__global__ void k2_scores(const float* __restrict__ mem) {
    const int b = blockIdx.y, tid = threadIdx.x;
    const int warp = tid >> 5, lane = tid & 31;
    const int n0 = blockIdx.x * 64 + warp * 8;
    const float4* mp = reinterpret_cast<const float4*>(mem)
                       + ((size_t)b * N_ + n0) * (DK_ / 4) + lane;
    float4 m[8];
#pragma unroll
    for (int r = 0; r < 8; r++) m[r] = __ldcs(mp + 32 * r);   // evict-first

    cudaTriggerProgrammaticLaunchCompletion();   // let k4 launch + prefetch prev
    cudaGridDependencySynchronize();             // wait for k1's g_q

    const float4 q4 = *reinterpret_cast<const float4*>(g_q + (size_t)b * DK_ + lane * 4);
    float d[8];
#pragma unroll
    for (int r = 0; r < 8; r++)
        d[r] = m[r].x * q4.x + m[r].y * q4.y + m[r].z * q4.z + m[r].w * q4.w;
#pragma unroll
    for (int r = 0; r < 8; r++) d[r] = warp_sum(d[r]);
    if (lane == 0) {
        float e[8];
#pragma unroll
        for (int r = 0; r < 8; r++) e[r] = __expf(d[r]);
        float* sc = g_escores + (size_t)b * N_ + n0;
        *reinterpret_cast<float4*>(sc)     = make_float4(e[0], e[1], e[2], e[3]);
        *reinterpret_cast<float4*>(sc + 4) = make_float4(e[4], e[5], e[6], e[7]);
        float t = 0.f;
#pragma unroll
        for (int r = 0; r < 8; r++) t += e[r];
        g_partial[b * KP_ + blockIdx.x * 8 + warp] = t;  // fixed slot -> deterministic
    }
}

// ---- K4: fused Z-reduce + interp + 5-tap circular shift, 2048 elems/block ----
__global__ void k4_out(const float* __restrict__ prev, float* __restrict__ out) {
    __shared__ float s_int[TILE_ + 8];
    __shared__ float s_sh[NS_];
    __shared__ float s_red[8];
    __shared__ float s_c[2];
    const int b = blockIdx.y, tid = threadIdx.x;
    const int warp = tid >> 5, lane = tid & 31;
    const int base = blockIdx.x * TILE_;

    // independent of k2: prev body + halo (read-once -> evict-first)
    const float4* pp = reinterpret_cast<const float4*>(prev + (size_t)b * N_ + base);
    float4 pr[TILE_ / 1024];
#pragma unroll
    for (int i = 0; i < TILE_ / 1024; i++) pr[i] = __ldcs(pp + tid + i * 256);
    float pr_halo = 0.f;
    int hk = 0;
    if (tid < 4) {
        hk = (tid < 2) ? (tid - 2) : (TILE_ + tid - 2);
        pr_halo = prev[(size_t)b * N_ + ((base + hk + N_) & (N_ - 1))];
    }

    cudaGridDependencySynchronize();   // wait for k2

    // issue escores loads FIRST (registers), Z-reduce hides under them
    const float4* ep = reinterpret_cast<const float4*>(g_escores + (size_t)b * N_ + base);
    float4 ev[TILE_ / 1024];
#pragma unroll
    for (int i = 0; i < TILE_ / 1024; i++) ev[i] = __ldcs(ep + tid + i * 256);
    float e_halo = 0.f;
    if (tid < 4) e_halo = g_escores[(size_t)b * N_ + ((base + hk + N_) & (N_ - 1))];

    // deterministic Z reduce over 1024 per-warp partials
    float p = 0.f;
    const float* gp = g_partial + (size_t)b * KP_;
#pragma unroll
    for (int i = 0; i < 4; i++) p += gp[tid + i * 256];
    p = warp_sum(p);
    if (lane == 0) s_red[warp] = p;
    if (tid < NS_) s_sh[tid] = g_shift[b * NS_ + tid];
    __syncthreads();
    if (tid == 0) {
        float Z = 0.f;
#pragma unroll
        for (int w = 0; w < 8; w++) Z += s_red[w];
        const float g = g_gate[b];
        s_c[0] = g / Z;
        s_c[1] = 1.f - g;
    }
    __syncthreads();
    const float cA = s_c[0], cB = s_c[1];

#pragma unroll
    for (int i = 0; i < TILE_ / 1024; i++) {
        const int v = tid + i * 256;
        float4 r;
        r.x = cA * ev[i].x + cB * pr[i].x;
        r.y = cA * ev[i].y + cB * pr[i].y;
        r.z = cA * ev[i].z + cB * pr[i].z;
        r.w = cA * ev[i].w + cB * pr[i].w;
        *reinterpret_cast<float4*>(s_int + 4 + v * 4) = r;
    }
    if (tid < 4) s_int[4 + hk] = cA * e_halo + cB * pr_halo;
    __syncthreads();

    const float sh0 = s_sh[0], sh1 = s_sh[1], sh2 = s_sh[2], sh3 = s_sh[3], sh4 = s_sh[4];
    float4* op = reinterpret_cast<float4*>(out + (size_t)b * N_ + base);
    const float4* si4 = reinterpret_cast<const float4*>(s_int);
#pragma unroll
    for (int i = 0; i < TILE_ / 1024; i++) {
        const int v = tid + i * 256;
        const float4 f0 = si4[v];
        const float4 f1 = si4[v + 1];
        const float4 f2 = si4[v + 2];
        float4 o;
        o.x = sh0 * f0.z + sh1 * f0.w + sh2 * f1.x + sh3 * f1.y + sh4 * f1.z;
        o.y = sh0 * f0.w + sh1 * f1.x + sh2 * f1.y + sh3 * f1.z + sh4 * f1.w;
        o.z = sh0 * f1.x + sh1 * f1.y + sh2 * f1.z + sh3 * f1.w + sh4 * f2.x;
        o.w = sh0 * f1.y + sh1 * f1.z + sh2 * f1.w + sh3 * f2.x + sh4 * f2.y;
        __stcs(op + v, o);
    }
}

extern "C" void kernel_launch(void* const* d_in, const int* in_sizes, int n_in,
                              void* d_out, int out_size) {
    const float* inp  = (const float*)d_in[0];
    const float* mem  = (const float*)d_in[1];
    const float* prev = (const float*)d_in[2];
    const float* W    = (const float*)d_in[3];
    const float* bias = (const float*)d_in[4];
    float* out = (float*)d_out;

    k1_head<<<dim3(17, B_ / BB_), 256>>>(inp, W, bias);

    cudaLaunchAttribute attrs[1];
    attrs[0].id = cudaLaunchAttributeProgrammaticStreamSerialization;
    attrs[0].val.programmaticStreamSerializationAllowed = 1;

    {
        cudaLaunchConfig_t cfg = {};
        cfg.gridDim = dim3(N_ / 64, B_);
        cfg.blockDim = dim3(256, 1, 1);
        cfg.attrs = attrs;
        cfg.numAttrs = 1;
        cudaLaunchKernelEx(&cfg, k2_scores, mem);
    }
    {
        cudaLaunchConfig_t cfg = {};
        cfg.gridDim = dim3(N_ / TILE_, B_);
        cfg.blockDim = dim3(256, 1, 1);
        cfg.attrs = attrs;
        cfg.numAttrs = 1;
        cudaLaunchKernelEx(&cfg, k4_out, prev, out);
    }
}

// round 16
// speedup vs baseline: 1.7629x; 1.0086x over previous
#include <cuda_runtime.h>
#include <cuda_fp16.h>

#define B_    256
#define N_    8192
#define DK_   128
#define DIN_  512
#define OUTD_ 134
#define NS_   5
#define TILE_ 2048   // elements per k4 block
#define BB_   8      // batches per k1 block
#define KP_   1024   // per-warp partials per batch (128 blocks x 8 warps)

// ---- device scratch ----
__device__ __half g_escores[B_ * N_];     // exp(score) in fp16 (range [e-6,e6]; Z in fp32)
__device__ float  g_q[B_ * DK_];          // query pre-scaled by 1/sqrt(dk)
__device__ float  g_shift[B_ * NS_];
__device__ float  g_gate[B_];
__device__ float  g_partial[B_ * KP_];

__device__ __forceinline__ float warp_sum(float v) {
#pragma unroll
    for (int o = 16; o; o >>= 1) v += __shfl_xor_sync(0xffffffffu, v, o);
    return v;
}

// ---- K1: head GEMM with 8-batch W reuse; grid (17, 32), 256 threads ----
__global__ void k1_head(const float* __restrict__ inp,
                        const float* __restrict__ W,
                        const float* __restrict__ bias) {
    cudaTriggerProgrammaticLaunchCompletion();

    __shared__ float s_in[BB_][DIN_];
    __shared__ float s_tail[BB_][6];
    const int tid = threadIdx.x;
    const int warp = tid >> 5, lane = tid & 31;
    const int b0 = blockIdx.y * BB_;
    const int o = blockIdx.x * 8 + warp;

    // issue W loads first (independent of smem / barrier)
    float4 w[4];
    if (o < OUTD_) {
        const float4* wr = reinterpret_cast<const float4*>(W + (size_t)o * DIN_);
#pragma unroll
        for (int j = 0; j < 4; j++) w[j] = wr[lane + 32 * j];
    }
    const float bo = (o < OUTD_) ? bias[o] : 0.f;

    {
        const float4* ip = reinterpret_cast<const float4*>(inp + (size_t)b0 * DIN_);
        float4* sp = &reinterpret_cast<float4(*)[DIN_ / 4]>(s_in)[0][0];
#pragma unroll
        for (int i = 0; i < 4; i++) sp[tid + i * 256] = ip[tid + i * 256];
    }
    __syncthreads();

    if (o < OUTD_) {
        float acc[BB_];
#pragma unroll
        for (int bb = 0; bb < BB_; bb++) acc[bb] = 0.f;
#pragma unroll
        for (int j = 0; j < 4; j++) {
#pragma unroll
            for (int bb = 0; bb < BB_; bb++) {
                const float4 x = reinterpret_cast<const float4*>(s_in[bb])[lane + 32 * j];
                acc[bb] = fmaf(w[j].x, x.x,
                           fmaf(w[j].y, x.y,
                            fmaf(w[j].z, x.z,
                             fmaf(w[j].w, x.w, acc[bb]))));
            }
        }
#pragma unroll
        for (int bb = 0; bb < BB_; bb++) {
            float s = warp_sum(acc[bb]);
            if (lane == 0) {
                s += bo;
                if (o < DK_)
                    g_q[(size_t)(b0 + bb) * DK_ + o] = s * 0.088388347648318447f;
                else
                    s_tail[bb][o - DK_] = s;
            }
        }
    }
    if (blockIdx.x == 16) {
        __syncthreads();
        if (tid < BB_) {
            const int b = b0 + tid;
            g_gate[b] = 1.f / (1.f + __expf(-s_tail[tid][0]));
            float mx = s_tail[tid][1];
#pragma unroll
            for (int s = 2; s <= NS_; s++) mx = fmaxf(mx, s_tail[tid][s]);
            float e[NS_], sum = 0.f;
#pragma unroll
            for (int s = 0; s < NS_; s++) { e[s] = __expf(s_tail[tid][1 + s] - mx); sum += e[s]; }
            float inv = 1.f / sum;
#pragma unroll
            for (int s = 0; s < NS_; s++) g_shift[b * NS_ + s] = e[s] * inv;
        }
    }
}

// ---- K2: streaming scores -> fp16 escores; fp32 partial sums; PDL both ways ----
__global__ void k2_scores(const float* __restrict__ mem) {
    const int b = blockIdx.y, tid = threadIdx.x;
    const int warp = tid >> 5, lane = tid & 31;
    const int n0 = blockIdx.x * 64 + warp * 8;
    const float4* mp = reinterpret_cast<const float4*>(mem)
                       + ((size_t)b * N_ + n0) * (DK_ / 4) + lane;
    float4 m[8];
#pragma unroll
    for (int r = 0; r < 8; r++) m[r] = __ldcs(mp + 32 * r);   // evict-first

    cudaTriggerProgrammaticLaunchCompletion();   // let k4 launch + prefetch prev
    cudaGridDependencySynchronize();             // wait for k1's g_q

    const float4 q4 = *reinterpret_cast<const float4*>(g_q + (size_t)b * DK_ + lane * 4);
    float d[8];
#pragma unroll
    for (int r = 0; r < 8; r++)
        d[r] = m[r].x * q4.x + m[r].y * q4.y + m[r].z * q4.z + m[r].w * q4.w;
#pragma unroll
    for (int r = 0; r < 8; r++) d[r] = warp_sum(d[r]);
    if (lane == 0) {
        float e[8];
#pragma unroll
        for (int r = 0; r < 8; r++) e[r] = __expf(d[r]);
        // pack 8 fp16 into one 16B store
        __half2 h0 = __floats2half2_rn(e[0], e[1]);
        __half2 h1 = __floats2half2_rn(e[2], e[3]);
        __half2 h2 = __floats2half2_rn(e[4], e[5]);
        __half2 h3 = __floats2half2_rn(e[6], e[7]);
        uint4 pk;
        pk.x = *reinterpret_cast<unsigned*>(&h0);
        pk.y = *reinterpret_cast<unsigned*>(&h1);
        pk.z = *reinterpret_cast<unsigned*>(&h2);
        pk.w = *reinterpret_cast<unsigned*>(&h3);
        *reinterpret_cast<uint4*>(g_escores + (size_t)b * N_ + n0) = pk;
        float t = 0.f;
#pragma unroll
        for (int r = 0; r < 8; r++) t += e[r];   // Z partial from fp32 values
        g_partial[b * KP_ + blockIdx.x * 8 + warp] = t;  // fixed slot -> deterministic
    }
}

// ---- K4: fused Z-reduce + interp + 5-tap circular shift, 2048 elems/block ----
__global__ void k4_out(const float* __restrict__ prev, float* __restrict__ out) {
    __shared__ float s_int[TILE_ + 8];
    __shared__ float s_sh[NS_];
    __shared__ float s_red[8];
    __shared__ float s_c[2];
    const int b = blockIdx.y, tid = threadIdx.x;
    const int warp = tid >> 5, lane = tid & 31;
    const int base = blockIdx.x * TILE_;

    // independent of k2: prev body + halo (thread t owns elements [8t, 8t+8))
    const float4* pp = reinterpret_cast<const float4*>(prev + (size_t)b * N_ + base);
    float4 pr0 = __ldcs(pp + 2 * tid);
    float4 pr1 = __ldcs(pp + 2 * tid + 1);
    float pr_halo = 0.f;
    int hk = 0;
    if (tid < 4) {
        hk = (tid < 2) ? (tid - 2) : (TILE_ + tid - 2);
        pr_halo = prev[(size_t)b * N_ + ((base + hk + N_) & (N_ - 1))];
    }

    cudaGridDependencySynchronize();   // wait for k2

    // escores (fp16): one uint4 = 8 halfs per thread, issued first
    const uint4* ep = reinterpret_cast<const uint4*>(g_escores + (size_t)b * N_ + base);
    const uint4 eu = __ldcs(ep + tid);
    float e_halo = 0.f;
    if (tid < 4) e_halo = __half2float(g_escores[(size_t)b * N_ + ((base + hk + N_) & (N_ - 1))]);

    // deterministic Z reduce over 1024 per-warp partials (hides under loads)
    float p = 0.f;
    const float* gp = g_partial + (size_t)b * KP_;
#pragma unroll
    for (int i = 0; i < 4; i++) p += gp[tid + i * 256];
    p = warp_sum(p);
    if (lane == 0) s_red[warp] = p;
    if (tid < NS_) s_sh[tid] = g_shift[b * NS_ + tid];
    __syncthreads();
    if (tid == 0) {
        float Z = 0.f;
#pragma unroll
        for (int w = 0; w < 8; w++) Z += s_red[w];
        const float g = g_gate[b];
        s_c[0] = g / Z;
        s_c[1] = 1.f - g;
    }
    __syncthreads();
    const float cA = s_c[0], cB = s_c[1];

    {
        const float2 f0 = __half22float2(*reinterpret_cast<const __half2*>(&eu.x));
        const float2 f1 = __half22float2(*reinterpret_cast<const __half2*>(&eu.y));
        const float2 f2 = __half22float2(*reinterpret_cast<const __half2*>(&eu.z));
        const float2 f3 = __half22float2(*reinterpret_cast<const __half2*>(&eu.w));
        float4 r0, r1;
        r0.x = cA * f0.x + cB * pr0.x;
        r0.y = cA * f0.y + cB * pr0.y;
        r0.z = cA * f1.x + cB * pr0.z;
        r0.w = cA * f1.y + cB * pr0.w;
        r1.x = cA * f2.x + cB * pr1.x;
        r1.y = cA * f2.y + cB * pr1.y;
        r1.z = cA * f3.x + cB * pr1.z;
        r1.w = cA * f3.y + cB * pr1.w;
        float4* si = reinterpret_cast<float4*>(s_int + 4 + tid * 8);  // 16B aligned
        si[0] = r0;
        si[1] = r1;
    }
    if (tid < 4) s_int[4 + hk] = cA * e_halo + cB * pr_halo;
    __syncthreads();

    const float sh0 = s_sh[0], sh1 = s_sh[1], sh2 = s_sh[2], sh3 = s_sh[3], sh4 = s_sh[4];
    float4* op = reinterpret_cast<float4*>(out + (size_t)b * N_ + base);
    const float4* si4 = reinterpret_cast<const float4*>(s_int);
#pragma unroll
    for (int i = 0; i < TILE_ / 1024; i++) {
        const int v = tid + i * 256;
        const float4 f0 = si4[v];
        const float4 f1 = si4[v + 1];
        const float4 f2 = si4[v + 2];
        float4 o;
        o.x = sh0 * f0.z + sh1 * f0.w + sh2 * f1.x + sh3 * f1.y + sh4 * f1.z;
        o.y = sh0 * f0.w + sh1 * f1.x + sh2 * f1.y + sh3 * f1.z + sh4 * f1.w;
        o.z = sh0 * f1.x + sh1 * f1.y + sh2 * f1.z + sh3 * f1.w + sh4 * f2.x;
        o.w = sh0 * f1.y + sh1 * f1.z + sh2 * f1.w + sh3 * f2.x + sh4 * f2.y;
        __stcs(op + v, o);
    }
}

extern "C" void kernel_launch(void* const* d_in, const int* in_sizes, int n_in,
                              void* d_out, int out_size) {
    const float* inp  = (const float*)d_in[0];
    const float* mem  = (const float*)d_in[1];
    const float* prev = (const float*)d_in[2];
    const float* W    = (const float*)d_in[3];
    const float* bias = (const float*)d_in[4];
    float* out = (float*)d_out;

    k1_head<<<dim3(17, B_ / BB_), 256>>>(inp, W, bias);

    cudaLaunchAttribute attrs[1];
    attrs[0].id = cudaLaunchAttributeProgrammaticStreamSerialization;
    attrs[0].val.programmaticStreamSerializationAllowed = 1;

    {
        cudaLaunchConfig_t cfg = {};
        cfg.gridDim = dim3(N_ / 64, B_);
        cfg.blockDim = dim3(256, 1, 1);
        cfg.attrs = attrs;
        cfg.numAttrs = 1;
        cudaLaunchKernelEx(&cfg, k2_scores, mem);
    }
    {
        cudaLaunchConfig_t cfg = {};
        cfg.gridDim = dim3(N_ / TILE_, B_);
        cfg.blockDim = dim3(256, 1, 1);
        cfg.attrs = attrs;
        cfg.numAttrs = 1;
        cudaLaunchKernelEx(&cfg, k4_out, prev, out);
    }
}